// round 9
// baseline (speedup 1.0000x reference)
#include <cuda_runtime.h>
#include <cuda_fp16.h>
#include <cstdint>

#define BATCH   524288
#define DIM     64
#define NE      8
#define NH      64
#define GHID    32

#define TILE_M  128
#define NTILES  (BATCH / TILE_M)   // 4096
#define GRID    296                // 2 CTAs per SM
#define THREADS 256
#define NSUB    8

// ---------------- smem byte layout ----------------
#define OFF_XHI    0        // fp16 [128][64] SW128 = 16384
#define OFF_GW1    16384    // fp32 [32][32] = 4096
#define OFF_GW2    20480    // fp32 [32][8] = 1024
#define OFF_GB1    21504    // fp32 [32] = 128
#define OFF_GB2    21632    // fp32 [8] = 32
#define OFF_PROB   21664    // fp32 [128][9] = 4608 (pitch 9, conflict-free)
#define OFF_EO     26272    // fp32 [128][9] = 4608
#define OFF_W2S    30880    // fp32 [8][64] = 2048
#define OFF_B1S    32928    // fp32 [8][64] = 2048
#define SMEM_BYTES 34976

#define SW(o) ((o) ^ (((o) >> 3) & 0x70))

static __device__ __forceinline__ uint32_t smem_u32(const void* p) {
    uint32_t a;
    asm("{ .reg .u64 t; cvta.to.shared.u64 t, %1; cvt.u32.u64 %0, t; }" : "=r"(a) : "l"(p));
    return a;
}
static __device__ __forceinline__ void ldsm4(uint32_t* r, uint32_t addr) {
    asm volatile("ldmatrix.sync.aligned.m8n8.x4.shared.b16 {%0,%1,%2,%3}, [%4];"
                 : "=r"(r[0]), "=r"(r[1]), "=r"(r[2]), "=r"(r[3]) : "r"(addr));
}
static __device__ __forceinline__ void mma16816(float* c, const uint32_t* a,
                                                uint32_t b0, uint32_t b1) {
    asm volatile(
        "mma.sync.aligned.m16n8k16.row.col.f32.f16.f16.f32 "
        "{%0,%1,%2,%3}, {%4,%5,%6,%7}, {%8,%9}, {%0,%1,%2,%3};"
        : "+f"(c[0]), "+f"(c[1]), "+f"(c[2]), "+f"(c[3])
        : "r"(a[0]), "r"(a[1]), "r"(a[2]), "r"(a[3]), "r"(b0), "r"(b1));
}

typedef unsigned long long ull;
static __device__ __forceinline__ ull fma2(ull a, ull b, ull c) {
    ull d;
    asm("fma.rn.f32x2 %0, %1, %2, %3;" : "=l"(d) : "l"(a), "l"(b), "l"(c));
    return d;
}
static __device__ __forceinline__ ull pack2(float x, float y) {
    ull d;
    asm("mov.b64 %0, {%1, %2};" : "=l"(d) : "f"(x), "f"(y));
    return d;
}
static __device__ __forceinline__ void unpack2(ull v, float& x, float& y) {
    asm("mov.b64 {%0, %1}, %2;" : "=f"(x), "=f"(y) : "l"(v));
}
static __device__ __forceinline__ uint32_t packh2(float a, float b) {
    __half ha = __float2half_rn(a), hb = __float2half_rn(b);
    return ((uint32_t)__half_as_ushort(hb) << 16) | __half_as_ushort(ha);
}
static __device__ __forceinline__ uint32_t cvth2(float a, float b) {
    uint32_t r;
    asm("cvt.rn.f16x2.f32 %0, %1, %2;" : "=r"(r) : "f"(b), "f"(a));
    return r;
}

__global__ void __launch_bounds__(THREADS, 2)
moe_mma_kernel(const float* __restrict__ A,   const float* __restrict__ S,
               const float* __restrict__ gw1, const float* __restrict__ gb1,
               const float* __restrict__ gw2, const float* __restrict__ gb2,
               const float* __restrict__ ew1, const float* __restrict__ eb1,
               const float* __restrict__ ew2, const float* __restrict__ eb2,
               float* __restrict__ out)
{
    extern __shared__ char smem[];
    float* smf = (float*)smem;
    const uint32_t sbase = smem_u32(smem);
    const int tid  = threadIdx.x;
    const int lane = tid & 31;
    const int wid  = tid >> 5;          // warp == expert id

    // ---- stage small fp32 weights ----
    for (int i = tid; i < GHID * GHID; i += THREADS) smf[OFF_GW1 / 4 + i] = gw1[i];
    for (int i = tid; i < GHID * NE;   i += THREADS) smf[OFF_GW2 / 4 + i] = gw2[i];
    for (int i = tid; i < NE * NH;     i += THREADS) {
        smf[OFF_W2S / 4 + i] = ew2[i];
        smf[OFF_B1S / 4 + i] = eb1[i];
    }
    if (tid < GHID) smf[OFF_GB1 / 4 + tid] = gb1[tid];
    if (tid < NE)   smf[OFF_GB2 / 4 + tid] = gb2[tid];
    const float b2v = eb2[wid];

    // ---- expert W1 B-fragments in registers (fp16, single rounding) ----
    uint32_t bh[8][4][2];
    {
        const float* we = ew1 + wid * DIM * NH;
        const int n  = (lane >> 2);
        const int kb = (lane & 3) * 2;
        #pragma unroll
        for (int nf = 0; nf < 8; nf++) {
            #pragma unroll
            for (int kk = 0; kk < 4; kk++) {
                const int k0 = kk * 16 + kb;
                bh[nf][kk][0] = packh2(we[(k0 + 0) * NH + nf * 8 + n],
                                       we[(k0 + 1) * NH + nf * 8 + n]);
                bh[nf][kk][1] = packh2(we[(k0 + 8) * NH + nf * 8 + n],
                                       we[(k0 + 9) * NH + nf * 8 + n]);
            }
        }
    }
    __syncthreads();

    const int rl = (lane & 7) + ((lane >> 3) & 1) * 8;
    const uint32_t pb  = (uint32_t)(rl * 128 + ((lane >> 4) * 16));
    const uint32_t swt = ((uint32_t)(rl * 128) >> 3) & 0x70;
    // convert (warps 4-7): 128 threads cover 128 rows x 16 float4-chunks in 16 iters
    const int ct   = tid - 128;          // 0..127 for warps 4-7
    const int crow = ct >> 3;            // 0..15 base row
    const int cc4h = ct & 7;             // chunk pair base

    // epilogue float2 pointers (pairs are adjacent in W2S/B1S)
    const float2* b1p = (const float2*)(smem + OFF_B1S) + wid * 32 + (lane & 3);
    const float2* w2p = (const float2*)(smem + OFF_W2S) + wid * 32 + (lane & 3);

    for (int tile = blockIdx.x; tile < NTILES; tile += GRID) {
        const int rowBase = tile * TILE_M;

        if (wid >= 4) {
            // ---- convert: LDG.128 -> fp16 -> SW128 XHI (warps 4-7 do all rows) ----
            #pragma unroll
            for (int w = 0; w < 16; w++) {
                int i = ct + w * 128;            // 0..2047
                int row = i >> 4, c4 = i & 15;
                const float4* src = (c4 < 8)
                    ? (const float4*)(A + (rowBase + row) * 32) + c4
                    : (const float4*)(S + (rowBase + row) * 32) + (c4 - 8);
                float4 v = *src;
                uint2 hp;
                hp.x = cvth2(v.x, v.y);
                hp.y = cvth2(v.z, v.w);
                *(uint2*)(smem + OFF_XHI + SW((uint32_t)(row * 128 + c4 * 8))) = hp;
            }
        } else {
            // ---- gating (warps 0-3): own row, S re-read from gmem (L1-hit) ----
            const float4* srow = (const float4*)(S + (rowBase + tid) * 32);
            ull h2[16];
            #pragma unroll
            for (int p = 0; p < 16; p++)
                h2[p] = *(const ull*)(smf + OFF_GB1 / 4 + 2 * p);
            #pragma unroll
            for (int kc = 0; kc < 4; kc++) {
                float4 va = srow[kc * 2], vb = srow[kc * 2 + 1];
                float sv[8] = {va.x, va.y, va.z, va.w, vb.x, vb.y, vb.z, vb.w};
                #pragma unroll
                for (int kj = 0; kj < 8; kj++) {
                    int k = kc * 8 + kj;
                    ull s2 = pack2(sv[kj], sv[kj]);
                    const ulonglong2* wr = (const ulonglong2*)(smem + OFF_GW1 + k * 128);
                    #pragma unroll
                    for (int j = 0; j < 8; j++) {
                        ulonglong2 w = wr[j];
                        h2[2 * j]     = fma2(s2, w.x, h2[2 * j]);
                        h2[2 * j + 1] = fma2(s2, w.y, h2[2 * j + 1]);
                    }
                }
            }
            ull l2[4];
            {
                ulonglong2 b = *(const ulonglong2*)(smem + OFF_GB2);
                l2[0] = b.x; l2[1] = b.y;
                b = *(const ulonglong2*)(smem + OFF_GB2 + 16);
                l2[2] = b.x; l2[3] = b.y;
            }
            #pragma unroll
            for (int p = 0; p < 16; p++) {
                float a, b; unpack2(h2[p], a, b);
                a = fmaxf(a, 0.f); b = fmaxf(b, 0.f);
                ull pa = pack2(a, a), pb2 = pack2(b, b);
                ulonglong2 wa0 = *(const ulonglong2*)(smem + OFF_GW2 + (2 * p) * 32);
                ulonglong2 wa1 = *(const ulonglong2*)(smem + OFF_GW2 + (2 * p) * 32 + 16);
                ulonglong2 wb0 = *(const ulonglong2*)(smem + OFF_GW2 + (2 * p + 1) * 32);
                ulonglong2 wb1 = *(const ulonglong2*)(smem + OFF_GW2 + (2 * p + 1) * 32 + 16);
                l2[0] = fma2(pa, wa0.x, l2[0]); l2[1] = fma2(pa, wa0.y, l2[1]);
                l2[2] = fma2(pa, wa1.x, l2[2]); l2[3] = fma2(pa, wa1.y, l2[3]);
                l2[0] = fma2(pb2, wb0.x, l2[0]); l2[1] = fma2(pb2, wb0.y, l2[1]);
                l2[2] = fma2(pb2, wb1.x, l2[2]); l2[3] = fma2(pb2, wb1.y, l2[3]);
            }
            float logit[NE];
            #pragma unroll
            for (int e2 = 0; e2 < 4; e2++) unpack2(l2[e2], logit[2 * e2], logit[2 * e2 + 1]);
            float mx = logit[0];
            #pragma unroll
            for (int e = 1; e < NE; e++) mx = fmaxf(mx, logit[e]);
            float se = 0.f, pr[NE];
            #pragma unroll
            for (int e = 0; e < NE; e++) { pr[e] = __expf(logit[e] - mx); se += pr[e]; }
            float inv = __fdividef(1.f, se);
            #pragma unroll
            for (int e = 0; e < NE; e++) smf[OFF_PROB / 4 + tid * 9 + e] = pr[e] * inv;
        }
        __syncthreads();   // barrier 1: XHI ready (and PROB written)

        // ---- expert GEMM: single fp16 product, warp = expert ----
        #pragma unroll 1
        for (int sub = 0; sub < NSUB; sub++) {
            float c[8][4];
            #pragma unroll
            for (int nf = 0; nf < 8; nf++) {
                float2 b = b1p[nf * 4];
                c[nf][0] = b.x; c[nf][1] = b.y; c[nf][2] = b.x; c[nf][3] = b.y;
            }
            #pragma unroll
            for (int kk = 0; kk < 4; kk++) {
                uint32_t ah[4];
                uint32_t off = (uint32_t)(sub * 2048) + ((pb + kk * 32) ^ swt);
                ldsm4(ah, sbase + OFF_XHI + off);
                #pragma unroll
                for (int nf = 0; nf < 8; nf++) mma16816(c[nf], ah, bh[nf][kk][0], bh[nf][kk][1]);
            }
            float p0 = 0.f, p1 = 0.f;
            #pragma unroll
            for (int nf = 0; nf < 8; nf++) {
                float2 w = w2p[nf * 4];
                p0 = fmaf(fmaxf(c[nf][0], 0.f), w.x, p0);
                p0 = fmaf(fmaxf(c[nf][1], 0.f), w.y, p0);
                p1 = fmaf(fmaxf(c[nf][2], 0.f), w.x, p1);
                p1 = fmaf(fmaxf(c[nf][3], 0.f), w.y, p1);
            }
            p0 += __shfl_xor_sync(0xFFFFFFFFu, p0, 1);
            p0 += __shfl_xor_sync(0xFFFFFFFFu, p0, 2);
            p1 += __shfl_xor_sync(0xFFFFFFFFu, p1, 1);
            p1 += __shfl_xor_sync(0xFFFFFFFFu, p1, 2);
            if ((lane & 3) == 0) {
                int r = sub * 16 + (lane >> 2);
                smf[OFF_EO / 4 + r * 9 + wid]       = p0 + b2v;
                smf[OFF_EO / 4 + (r + 8) * 9 + wid] = p1 + b2v;
            }
        }
        __syncthreads();   // barrier 2: EO ready

        // ---- final: weighted sum over experts ----
        if (tid < TILE_M) {
            const float* pr = smf + OFF_PROB / 4 + tid * 9;
            const float* eo = smf + OFF_EO / 4 + tid * 9;
            float r = 0.f;
            #pragma unroll
            for (int e = 0; e < NE; e++) r = fmaf(pr[e], eo[e], r);
            out[rowBase + tid] = r;
        }
    }
}

extern "C" void kernel_launch(void* const* d_in, const int* in_sizes, int n_in,
                              void* d_out, int out_size)
{
    (void)in_sizes; (void)n_in; (void)out_size;
    const float* A   = (const float*)d_in[0];
    const float* S   = (const float*)d_in[1];
    const float* gw1 = (const float*)d_in[2];
    const float* gb1 = (const float*)d_in[3];
    const float* gw2 = (const float*)d_in[4];
    const float* gb2 = (const float*)d_in[5];
    const float* ew1 = (const float*)d_in[6];
    const float* eb1 = (const float*)d_in[7];
    const float* ew2 = (const float*)d_in[8];
    const float* eb2 = (const float*)d_in[9];
    float* out = (float*)d_out;

    cudaFuncSetAttribute(moe_mma_kernel, cudaFuncAttributeMaxDynamicSharedMemorySize, SMEM_BYTES);
    moe_mma_kernel<<<GRID, THREADS, SMEM_BYTES>>>(
        A, S, gw1, gb1, gw2, gb2, ew1, eb1, ew2, eb2, out);
}